// round 13
// baseline (speedup 1.0000x reference)
#include <cuda_runtime.h>

// FraudDetectionModel R13: 2 graph nodes + PDL overlap.
//  R12 confirmed: LDC params = 32.3us main kernel (HBM floor), but the
//  serialized fold-node cost 4.2us of graph overhead. Fix: programmatic
//  dependent launch. Fold kernel signals launch_dependents right after its
//  stores; main kernel launches with ProgrammaticStreamSerialization, issues
//  its data LDGs, THEN griddepcontrol.wait before the first LDC. Constant
//  cache is per-launch-invalidated and lazily filled at first LDC (strictly
//  after the wait), so it observes the fold's L2-visible writes.

#define BATCH   16777216
#define THREADS 256
#define ROWS_PER_THREAD 4

// Folded params: layer l (0..3) at [6l]: w00 w01 w10 w11 b0 b1 ; [24..26] wf0 wf1 bf
__constant__ float c_fold[28];

__device__ __forceinline__ float fast_tanh(float x) {
    float y;
    asm("tanh.approx.f32 %0, %1;" : "=f"(y) : "f"(x));
    return y;
}

// Lane-parallel fold into the constant symbol's backing store.
__global__ void fold_params_kernel(float* __restrict__ dst,          // = &c_fold backing
                                   const float* __restrict__ Ws,     // [4,2,2]
                                   const float* __restrict__ bs,     // [4,2]
                                   const float* __restrict__ sc,     // [4,2]
                                   const float* __restrict__ sh,     // [4,2]
                                   const float* __restrict__ Wf,     // [1,2]
                                   const float* __restrict__ bf)     // [1]
{
    const int t = threadIdx.x;
    if (t < 27) {
        float v;
        if (t < 24) {
            const int l = t / 6;          // layer
            const int j = t % 6;          // 0..3 W, 4..5 bias
            if (l == 0) {
                v = (j < 4) ? Ws[j] : bs[j - 4];
            } else if (j < 4) {
                v = Ws[l * 4 + j] * sc[(l - 1) * 2 + (j & 1)];
            } else {
                const int row = j - 4;
                v = fmaf(Ws[l * 4 + row * 2 + 0], sh[(l - 1) * 2 + 0],
                    fmaf(Ws[l * 4 + row * 2 + 1], sh[(l - 1) * 2 + 1],
                         bs[l * 2 + row]));
            }
        } else if (t == 24) {
            v = Wf[0] * sc[6];
        } else if (t == 25) {
            v = Wf[1] * sc[7];
        } else {
            v = fmaf(Wf[0], sh[6], fmaf(Wf[1], sh[7], bf[0]));
        }
        dst[t] = v;
        __threadfence();
    }
    // Allow the dependent (main) grid to launch now; its griddepcontrol.wait
    // guarantees visibility of the stores above.
    asm volatile("griddepcontrol.launch_dependents;");
}

__global__ void __launch_bounds__(THREADS)
fraud_mlp_kernel(const float4* __restrict__ x,    // [B/2] row pairs
                 float4*       __restrict__ out)  // [B/4] quad outputs
{
    const int i = blockIdx.x * blockDim.x + threadIdx.x;

    // Data loads are independent of the fold: issue them BEFORE the grid
    // dependency wait so they overlap the fold kernel's tail.
    const float4 xv0 = x[2 * i + 0];   // rows 0,1
    const float4 xv1 = x[2 * i + 1];   // rows 2,3

    // Block until the fold grid's memory is visible; no LDC before this.
    asm volatile("griddepcontrol.wait;" ::: "memory");

    float ha[4], hb[4];
    ha[0] = xv0.x; hb[0] = xv0.y;  ha[1] = xv0.z; hb[1] = xv0.w;
    ha[2] = xv1.x; hb[2] = xv1.y;  ha[3] = xv1.z; hb[3] = xv1.w;

#pragma unroll
    for (int l = 0; l < 4; l++) {
        const float w00 = c_fold[l * 6 + 0], w01 = c_fold[l * 6 + 1];
        const float w10 = c_fold[l * 6 + 2], w11 = c_fold[l * 6 + 3];
        const float b0  = c_fold[l * 6 + 4], b1  = c_fold[l * 6 + 5];
#pragma unroll
        for (int r = 0; r < 4; r++) {
            float u0 = fmaf(w00, ha[r], fmaf(w01, hb[r], b0));
            float u1 = fmaf(w10, ha[r], fmaf(w11, hb[r], b1));
            ha[r] = fast_tanh(u0);
            hb[r] = fast_tanh(u1);
        }
    }

    const float wf0 = c_fold[24], wf1 = c_fold[25], bff = c_fold[26];

    float4 o;
    o.x = fmaf(wf0, ha[0], fmaf(wf1, hb[0], bff));
    o.y = fmaf(wf0, ha[1], fmaf(wf1, hb[1], bff));
    o.z = fmaf(wf0, ha[2], fmaf(wf1, hb[2], bff));
    o.w = fmaf(wf0, ha[3], fmaf(wf1, hb[3], bff));

    out[i] = o;
}

extern "C" void kernel_launch(void* const* d_in, const int* in_sizes, int n_in,
                              void* d_out, int out_size)
{
    const float4* x = (const float4*)d_in[0];
    float4* out = (float4*)d_out;

    void* c_addr = nullptr;
    cudaGetSymbolAddress(&c_addr, c_fold);

    fold_params_kernel<<<1, 32>>>(
        (float*)c_addr,
        (const float*)d_in[1], (const float*)d_in[2], (const float*)d_in[3],
        (const float*)d_in[4], (const float*)d_in[5], (const float*)d_in[6]);

    // Main kernel with programmatic dependent launch: overlaps its launch
    // and first load wave with the fold kernel.
    const int nthreads = BATCH / ROWS_PER_THREAD;   // 4,194,304
    const int blocks = nthreads / THREADS;          // 16384

    cudaLaunchAttribute attrs[1];
    attrs[0].id = cudaLaunchAttributeProgrammaticStreamSerialization;
    attrs[0].val.programmaticStreamSerializationAllowed = 1;

    cudaLaunchConfig_t cfg = {};
    cfg.gridDim = dim3(blocks, 1, 1);
    cfg.blockDim = dim3(THREADS, 1, 1);
    cfg.dynamicSmemBytes = 0;
    cfg.stream = 0;
    cfg.attrs = attrs;
    cfg.numAttrs = 1;

    cudaLaunchKernelEx(&cfg, fraud_mlp_kernel, x, out);
}